// round 10
// baseline (speedup 1.0000x reference)
#include <cuda_runtime.h>

// out[s, :] = W_tok[x[s], :] + b_tok + W_pos[(S-1)-s, :] + b_pos
// S = 8192, D = 1024, fp32.
// Persistent grid-stride kernel: grid = 148*8 = 1184 CTAs (one full wave at
// 8 CTAs/SM), each block loops over rows s = bid, bid+1184, ...  This removes
// the ~22% CTA-wave quantization idle of the flat 2048-CTA launch.
// Reads (W_tok gather + W_pos) pinned L2-resident via evict_last cache hint
// (fixed hot set across graph replays, verified win R5/R9); output store is
// evict-first (__stcs) so the write stream doesn't thrash the read set (R8).

#define EMBED 1024
#define VEC (EMBED / 4)     // 256 float4 per row
#define NBLK 1184           // 148 SMs * 8 CTAs

__device__ __forceinline__ float4 ldg_evict_last(const float4* p, unsigned long long pol) {
    float4 v;
    asm volatile("ld.global.nc.L2::cache_hint.v4.f32 {%0,%1,%2,%3}, [%4], %5;"
                 : "=f"(v.x), "=f"(v.y), "=f"(v.z), "=f"(v.w)
                 : "l"(p), "l"(pol));
    return v;
}

__global__ __launch_bounds__(256, 8) void embed_kernel(
    const int* __restrict__ x,
    const float4* __restrict__ W_tok,   // [VOCAB, VEC]
    const float4* __restrict__ b_tok,   // [VEC]
    const float4* __restrict__ W_pos,   // [MAX_CTX, VEC]
    const float4* __restrict__ b_pos,   // [VEC]
    float4* __restrict__ out,           // [S, VEC]
    int S)
{
    const int c = threadIdx.x;          // float4 column 0..255

    unsigned long long pol;
    asm("createpolicy.fractional.L2::evict_last.b64 %0, 1.0;" : "=l"(pol));

    // Hoist the combined bias once per block (x+pos biases are tiny, L2-hot)
    const float4 bt = __ldg(&b_tok[c]);
    const float4 bp = __ldg(&b_pos[c]);
    const float bx = bt.x + bp.x, by = bt.y + bp.y,
                bz = bt.z + bp.z, bw = bt.w + bp.w;

    for (int s = blockIdx.x; s < S; s += NBLK) {
        const int tok = __ldg(&x[s]);
        const int pos = (S - 1) - s;

        const float4 t = ldg_evict_last(&W_tok[(long long)tok * VEC + c], pol);
        const float4 p = ldg_evict_last(&W_pos[(long long)pos * VEC + c], pol);

        float4 r;
        r.x = t.x + p.x + bx;
        r.y = t.y + p.y + by;
        r.z = t.z + p.z + bz;
        r.w = t.w + p.w + bw;
        __stcs(&out[(long long)s * VEC + c], r);   // evict-first store
    }
}

extern "C" void kernel_launch(void* const* d_in, const int* in_sizes, int n_in,
                              void* d_out, int out_size)
{
    const int*    x     = (const int*)   d_in[0];
    const float4* W_tok = (const float4*)d_in[1];
    const float4* b_tok = (const float4*)d_in[2];
    const float4* W_pos = (const float4*)d_in[3];
    const float4* b_pos = (const float4*)d_in[4];
    float4* out = (float4*)d_out;

    const int S = in_sizes[0];          // 8192

    embed_kernel<<<NBLK, 256>>>(x, W_tok, b_tok, W_pos, b_pos, out, S);
}

// round 15
// speedup vs baseline: 1.1504x; 1.1504x over previous
#include <cuda_runtime.h>

// out[s, :] = W_tok[x[s], :] + b_tok + W_pos[(S-1)-s, :] + b_pos
// S = 8192, D = 1024, fp32.
// Flat launch, 2 rows per block (RPB=2), 256 threads x float4.
// Why RPB=2: RPB=4 @ 6 CTAs/SM quantizes 2048 CTAs into 3 rigid waves (23%
// idle); RPB=2 gives 4096 CTAs over ~1776 rows/wave -> 5 waves, ~8% idle,
// while still front-batching 4 independent LDG.128 per thread to hide L2-hit
// latency in the warm (L2-resident) regime. Persistent MLP=2 loop (R10)
// regressed -> front-batching is load-bearing.
// Reads pinned L2-resident (evict_last, fixed hot set across graph replays,
// R5/R9 win); output store evict-first (__stcs) so writes don't thrash it (R8).

#define EMBED 1024
#define VEC (EMBED / 4)     // 256 float4 per row
#define RPB 2               // rows per block

__device__ __forceinline__ float4 ldg_evict_last(const float4* p, unsigned long long pol) {
    float4 v;
    asm volatile("ld.global.nc.L2::cache_hint.v4.f32 {%0,%1,%2,%3}, [%4], %5;"
                 : "=f"(v.x), "=f"(v.y), "=f"(v.z), "=f"(v.w)
                 : "l"(p), "l"(pol));
    return v;
}

__global__ __launch_bounds__(256) void embed_kernel(
    const int* __restrict__ x,
    const float4* __restrict__ W_tok,   // [VOCAB, VEC]
    const float4* __restrict__ b_tok,   // [VEC]
    const float4* __restrict__ W_pos,   // [MAX_CTX, VEC]
    const float4* __restrict__ b_pos,   // [VEC]
    float4* __restrict__ out,           // [S, VEC]
    int S)
{
    const int s0 = blockIdx.x * RPB;
    const int c  = threadIdx.x;         // float4 column 0..255

    unsigned long long pol;
    asm("createpolicy.fractional.L2::evict_last.b64 %0, 1.0;" : "=l"(pol));

    int tok[RPB];
#pragma unroll
    for (int i = 0; i < RPB; i++)
        tok[i] = __ldg(&x[s0 + i]);

    // Front-batch all 4 big loads (pinned L2-resident)
    float4 t[RPB], p[RPB];
#pragma unroll
    for (int i = 0; i < RPB; i++)
        t[i] = ldg_evict_last(&W_tok[(long long)tok[i] * VEC + c], pol);
#pragma unroll
    for (int i = 0; i < RPB; i++) {
        const int pos = (S - 1) - (s0 + i);
        p[i] = ldg_evict_last(&W_pos[(long long)pos * VEC + c], pol);
    }

    const float4 bt = __ldg(&b_tok[c]);
    const float4 bp = __ldg(&b_pos[c]);
    const float bx = bt.x + bp.x, by = bt.y + bp.y,
                bz = bt.z + bp.z, bw = bt.w + bp.w;

#pragma unroll
    for (int i = 0; i < RPB; i++) {
        float4 r;
        r.x = t[i].x + p[i].x + bx;
        r.y = t[i].y + p[i].y + by;
        r.z = t[i].z + p[i].z + bz;
        r.w = t[i].w + p[i].w + bw;
        __stcs(&out[(long long)(s0 + i) * VEC + c], r);    // evict-first store
    }
}

extern "C" void kernel_launch(void* const* d_in, const int* in_sizes, int n_in,
                              void* d_out, int out_size)
{
    const int*    x     = (const int*)   d_in[0];
    const float4* W_tok = (const float4*)d_in[1];
    const float4* b_tok = (const float4*)d_in[2];
    const float4* W_pos = (const float4*)d_in[3];
    const float4* b_pos = (const float4*)d_in[4];
    float4* out = (float4*)d_out;

    const int S = in_sizes[0];          // 8192

    embed_kernel<<<S / RPB, 256>>>(x, W_tok, b_tok, W_pos, b_pos, out, S);
}